// round 12
// baseline (speedup 1.0000x reference)
#include <cuda_runtime.h>
#include <math.h>

#define BATCH 4
#define SEQ   2048
#define EMB   1024
#define NH    16
#define HD    64
#define MTOT  (BATCH*SEQ)

// Scratch (allocation-free rule: device globals)
__device__ float g_q[BATCH*NH*SEQ*HD];
__device__ float g_k[BATCH*NH*SEQ*HD];
__device__ float g_v[BATCH*NH*SEQ*HD];
__device__ float g_ao[MTOT*EMB];

#define BM 128
#define BN 128
#define BK 16

// ---------------------------------------------------------------------------
// QKV GEMM:  C[m,n] = sum_k hidden[m,k] * qkv_w[n,k] + qkv_b[n]
// Epilogue scatters into g_q / g_k / g_v in [B,H,S,hd] layout.
// ---------------------------------------------------------------------------
__global__ void __launch_bounds__(256) qkv_gemm(const float* __restrict__ A,
                                                const float* __restrict__ W,
                                                const float* __restrict__ bias)
{
    __shared__ float sA[BK][BM];
    __shared__ float sB[BK][BN];
    const int K = EMB;
    const int tid = threadIdx.x;
    const int m0 = blockIdx.y * BM;
    const int n0 = blockIdx.x * BN;
    const int tr = tid >> 4;
    const int tc = tid & 15;
    const int lr = tid >> 2;
    const int lc = (tid & 3) << 2;

    float acc[8][8];
#pragma unroll
    for (int i = 0; i < 8; i++)
#pragma unroll
        for (int j = 0; j < 8; j++) acc[i][j] = 0.f;

    const float* Ap = A + (size_t)(m0 + lr) * K + lc;
    const float* Wp = W + (size_t)(n0 + lr) * K + lc;

    for (int k0 = 0; k0 < K; k0 += BK) {
        float4 a0 = *(const float4*)(Ap + k0);
        float4 a1 = *(const float4*)(Ap + (size_t)64 * K + k0);
        float4 b0 = *(const float4*)(Wp + k0);
        float4 b1 = *(const float4*)(Wp + (size_t)64 * K + k0);
        __syncthreads();
        sA[lc+0][lr]    = a0.x; sA[lc+1][lr]    = a0.y; sA[lc+2][lr]    = a0.z; sA[lc+3][lr]    = a0.w;
        sA[lc+0][lr+64] = a1.x; sA[lc+1][lr+64] = a1.y; sA[lc+2][lr+64] = a1.z; sA[lc+3][lr+64] = a1.w;
        sB[lc+0][lr]    = b0.x; sB[lc+1][lr]    = b0.y; sB[lc+2][lr]    = b0.z; sB[lc+3][lr]    = b0.w;
        sB[lc+0][lr+64] = b1.x; sB[lc+1][lr+64] = b1.y; sB[lc+2][lr+64] = b1.z; sB[lc+3][lr+64] = b1.w;
        __syncthreads();
#pragma unroll
        for (int kk = 0; kk < BK; kk++) {
            float4 aL = *(const float4*)&sA[kk][tr*8];
            float4 aH = *(const float4*)&sA[kk][tr*8+4];
            float4 bL = *(const float4*)&sB[kk][tc*8];
            float4 bH = *(const float4*)&sB[kk][tc*8+4];
            float ar[8] = {aL.x,aL.y,aL.z,aL.w,aH.x,aH.y,aH.z,aH.w};
            float br[8] = {bL.x,bL.y,bL.z,bL.w,bH.x,bH.y,bH.z,bH.w};
#pragma unroll
            for (int i = 0; i < 8; i++)
#pragma unroll
                for (int j = 0; j < 8; j++)
                    acc[i][j] = fmaf(ar[i], br[j], acc[i][j]);
        }
    }

    // Epilogue: whole 128-wide N tile stays within one of q/k/v (E=1024 % 128 == 0),
    // and a thread's 8 columns stay within one head (64 % 8 == 0).
    const int which = n0 >> 10;
    float* dst = which == 0 ? g_q : (which == 1 ? g_k : g_v);
    const int bb   = m0 >> 11;                 // SEQ=2048, BM=128 -> tile within one batch
    const int rem0 = (n0 & 1023) + tc * 8;
    const int h    = rem0 >> 6;
    const int d0   = rem0 & 63;
    float4 bv0 = *(const float4*)&bias[n0 + tc*8];
    float4 bv1 = *(const float4*)&bias[n0 + tc*8 + 4];
#pragma unroll
    for (int mi = 0; mi < 8; mi++) {
        int m = m0 + tr * 8 + mi;
        int s = m & (SEQ - 1);
        float* p = dst + (((size_t)(bb * NH + h)) * SEQ + s) * HD + d0;
        float4 v0 = make_float4(acc[mi][0]+bv0.x, acc[mi][1]+bv0.y, acc[mi][2]+bv0.z, acc[mi][3]+bv0.w);
        float4 v1 = make_float4(acc[mi][4]+bv1.x, acc[mi][5]+bv1.y, acc[mi][6]+bv1.z, acc[mi][7]+bv1.w);
        *(float4*)p       = v0;
        *(float4*)(p + 4) = v1;
    }
}

// ---------------------------------------------------------------------------
// Output projection GEMM:  out[m,n] = sum_k g_ao[m,k] * proj_w[n,k] + proj_b[n]
// ---------------------------------------------------------------------------
__global__ void __launch_bounds__(256) proj_gemm(const float* __restrict__ W,
                                                 const float* __restrict__ bias,
                                                 float* __restrict__ C)
{
    __shared__ float sA[BK][BM];
    __shared__ float sB[BK][BN];
    const int K = EMB;
    const int tid = threadIdx.x;
    const int m0 = blockIdx.y * BM;
    const int n0 = blockIdx.x * BN;
    const int tr = tid >> 4;
    const int tc = tid & 15;
    const int lr = tid >> 2;
    const int lc = (tid & 3) << 2;

    float acc[8][8];
#pragma unroll
    for (int i = 0; i < 8; i++)
#pragma unroll
        for (int j = 0; j < 8; j++) acc[i][j] = 0.f;

    const float* Ap = g_ao + (size_t)(m0 + lr) * K + lc;
    const float* Wp = W    + (size_t)(n0 + lr) * K + lc;

    for (int k0 = 0; k0 < K; k0 += BK) {
        float4 a0 = *(const float4*)(Ap + k0);
        float4 a1 = *(const float4*)(Ap + (size_t)64 * K + k0);
        float4 b0 = *(const float4*)(Wp + k0);
        float4 b1 = *(const float4*)(Wp + (size_t)64 * K + k0);
        __syncthreads();
        sA[lc+0][lr]    = a0.x; sA[lc+1][lr]    = a0.y; sA[lc+2][lr]    = a0.z; sA[lc+3][lr]    = a0.w;
        sA[lc+0][lr+64] = a1.x; sA[lc+1][lr+64] = a1.y; sA[lc+2][lr+64] = a1.z; sA[lc+3][lr+64] = a1.w;
        sB[lc+0][lr]    = b0.x; sB[lc+1][lr]    = b0.y; sB[lc+2][lr]    = b0.z; sB[lc+3][lr]    = b0.w;
        sB[lc+0][lr+64] = b1.x; sB[lc+1][lr+64] = b1.y; sB[lc+2][lr+64] = b1.z; sB[lc+3][lr+64] = b1.w;
        __syncthreads();
#pragma unroll
        for (int kk = 0; kk < BK; kk++) {
            float4 aL = *(const float4*)&sA[kk][tr*8];
            float4 aH = *(const float4*)&sA[kk][tr*8+4];
            float4 bL = *(const float4*)&sB[kk][tc*8];
            float4 bH = *(const float4*)&sB[kk][tc*8+4];
            float ar[8] = {aL.x,aL.y,aL.z,aL.w,aH.x,aH.y,aH.z,aH.w};
            float br[8] = {bL.x,bL.y,bL.z,bL.w,bH.x,bH.y,bH.z,bH.w};
#pragma unroll
            for (int i = 0; i < 8; i++)
#pragma unroll
                for (int j = 0; j < 8; j++)
                    acc[i][j] = fmaf(ar[i], br[j], acc[i][j]);
        }
    }

    float4 bv0 = *(const float4*)&bias[n0 + tc*8];
    float4 bv1 = *(const float4*)&bias[n0 + tc*8 + 4];
#pragma unroll
    for (int mi = 0; mi < 8; mi++) {
        int m = m0 + tr * 8 + mi;
        float* p = C + (size_t)m * EMB + n0 + tc * 8;
        float4 v0 = make_float4(acc[mi][0]+bv0.x, acc[mi][1]+bv0.y, acc[mi][2]+bv0.z, acc[mi][3]+bv0.w);
        float4 v1 = make_float4(acc[mi][4]+bv1.x, acc[mi][5]+bv1.y, acc[mi][6]+bv1.z, acc[mi][7]+bv1.w);
        *(float4*)p       = v0;
        *(float4*)(p + 4) = v1;
    }
}

// ---------------------------------------------------------------------------
// RoPE in-place on g_q, g_k. hd=64: pair (j, j+32), j in [0,32).
// Angle in fp64 (cheap; removes trig-precision risk).
// ---------------------------------------------------------------------------
__global__ void rope_kernel()
{
    int t = blockIdx.x * blockDim.x + threadIdx.x;
    int j = t & 31;
    int bhs = t >> 5;
    int s = bhs & (SEQ - 1);
    double inv = exp(-(double)j * (9.210340371976184 / 32.0));  // 10000^(-j/32)
    double th = (double)s * inv;
    float c  = (float)cos(th);
    float si = (float)sin(th);
    float* q = g_q + (size_t)bhs * HD;
    float* k = g_k + (size_t)bhs * HD;
    float x1 = q[j], x2 = q[j + 32];
    q[j]      = x1 * c - x2 * si;
    q[j + 32] = x2 * c + x1 * si;
    x1 = k[j]; x2 = k[j + 32];
    k[j]      = x1 * c - x2 * si;
    k[j + 32] = x2 * c + x1 * si;
}

// ---------------------------------------------------------------------------
// Flash attention fp32. One CTA per (bh, 64-row q tile). 256 threads as 16x16,
// each owning a 4x4 micro-tile. 64 KB dynamic smem:
//   sQt[d][i], sKt[d][j] transposed for conflict-free float4 reads along i/j,
//   sV[j][e] natural, sPt[j][i] transposed for the P@V pass.
// ---------------------------------------------------------------------------
__global__ void __launch_bounds__(256) attn_kernel()
{
    extern __shared__ float sm[];
    float* sQt = sm;
    float* sKt = sm + 64*64;
    float* sV  = sm + 2*64*64;
    float* sPt = sm + 3*64*64;

    const int bh = blockIdx.y;
    const int q0 = blockIdx.x * 64;
    const float* Qg = g_q + ((size_t)bh * SEQ + q0) * HD;
    const float* Kg = g_k + (size_t)bh * SEQ * HD;
    const float* Vg = g_v + (size_t)bh * SEQ * HD;

    const int tid = threadIdx.x;
    const int ty = tid >> 4;
    const int tx = tid & 15;
    const int lrow  = tid >> 2;
    const int lcol4 = (tid & 3) * 4;

    // Load Q tile transposed: sQt[d][i]
#pragma unroll
    for (int rep = 0; rep < 4; rep++) {
        int col = lcol4 + rep * 16;
        float4 v = *(const float4*)&Qg[lrow * HD + col];
        sQt[(col+0)*64 + lrow] = v.x;
        sQt[(col+1)*64 + lrow] = v.y;
        sQt[(col+2)*64 + lrow] = v.z;
        sQt[(col+3)*64 + lrow] = v.w;
    }

    float o[4][4];
    float mrow[4], lsum[4];
#pragma unroll
    for (int i = 0; i < 4; i++) {
        mrow[i] = -1e30f; lsum[i] = 0.f;
#pragma unroll
        for (int e = 0; e < 4; e++) o[i][e] = 0.f;
    }

    for (int nt = 0; nt < SEQ / 64; nt++) {
        const float* Kt = Kg + (size_t)nt * 64 * HD;
        const float* Vt = Vg + (size_t)nt * 64 * HD;
        __syncthreads();   // prior P@V pass done with sV/sPt
#pragma unroll
        for (int rep = 0; rep < 4; rep++) {
            int col = lcol4 + rep * 16;
            float4 kv = *(const float4*)&Kt[lrow * HD + col];
            sKt[(col+0)*64 + lrow] = kv.x;
            sKt[(col+1)*64 + lrow] = kv.y;
            sKt[(col+2)*64 + lrow] = kv.z;
            sKt[(col+3)*64 + lrow] = kv.w;
            float4 vv = *(const float4*)&Vt[lrow * HD + col];
            *(float4*)&sV[lrow * 64 + col] = vv;
        }
        __syncthreads();

        // S = Q K^T
        float s4[4][4];
#pragma unroll
        for (int i = 0; i < 4; i++)
#pragma unroll
            for (int j = 0; j < 4; j++) s4[i][j] = 0.f;
#pragma unroll 16
        for (int d = 0; d < 64; d++) {
            float4 a = *(const float4*)&sQt[d*64 + ty*4];
            float4 b = *(const float4*)&sKt[d*64 + tx*4];
            float aa[4] = {a.x, a.y, a.z, a.w};
            float bb[4] = {b.x, b.y, b.z, b.w};
#pragma unroll
            for (int i = 0; i < 4; i++)
#pragma unroll
                for (int j = 0; j < 4; j++)
                    s4[i][j] = fmaf(aa[i], bb[j], s4[i][j]);
        }

        // Online softmax (row reduction across the 16 tx lanes)
#pragma unroll
        for (int i = 0; i < 4; i++) {
            float mx = -1e30f;
#pragma unroll
            for (int j = 0; j < 4; j++) { s4[i][j] *= 0.125f; mx = fmaxf(mx, s4[i][j]); }
#pragma unroll
            for (int off = 8; off; off >>= 1)
                mx = fmaxf(mx, __shfl_xor_sync(0xffffffffu, mx, off));
            float mnew  = fmaxf(mrow[i], mx);
            float alpha = __expf(mrow[i] - mnew);
            mrow[i] = mnew;
            float rs = 0.f;
#pragma unroll
            for (int j = 0; j < 4; j++) {
                float p = __expf(s4[i][j] - mnew);
                s4[i][j] = p;
                rs += p;
            }
#pragma unroll
            for (int off = 8; off; off >>= 1)
                rs += __shfl_xor_sync(0xffffffffu, rs, off);
            lsum[i] = lsum[i] * alpha + rs;
#pragma unroll
            for (int e = 0; e < 4; e++) o[i][e] *= alpha;
        }

        // Write P transposed: sPt[j][i]
#pragma unroll
        for (int j = 0; j < 4; j++) {
            float4 pv = make_float4(s4[0][j], s4[1][j], s4[2][j], s4[3][j]);
            *(float4*)&sPt[(tx*4 + j)*64 + ty*4] = pv;
        }
        __syncthreads();

        // O += P V
#pragma unroll 16
        for (int j = 0; j < 64; j++) {
            float4 p = *(const float4*)&sPt[j*64 + ty*4];
            float4 v = *(const float4*)&sV[j*64 + tx*4];
            float pa[4] = {p.x, p.y, p.z, p.w};
            float va[4] = {v.x, v.y, v.z, v.w};
#pragma unroll
            for (int i = 0; i < 4; i++)
#pragma unroll
                for (int e = 0; e < 4; e++)
                    o[i][e] = fmaf(pa[i], va[e], o[i][e]);
        }
    }

    // Epilogue: normalize and write [B,S,E] with E index = h*64 + e
    const int bidx = bh >> 4;
    const int h    = bh & 15;
#pragma unroll
    for (int i = 0; i < 4; i++) {
        float inv = 1.f / lsum[i];
        int s = q0 + ty * 4 + i;
        float4 ov = make_float4(o[i][0]*inv, o[i][1]*inv, o[i][2]*inv, o[i][3]*inv);
        *(float4*)&g_ao[((size_t)(bidx * SEQ + s)) * EMB + h * HD + tx * 4] = ov;
    }
}

// ---------------------------------------------------------------------------
extern "C" void kernel_launch(void* const* d_in, const int* in_sizes, int n_in,
                              void* d_out, int out_size)
{
    (void)in_sizes; (void)n_in; (void)out_size;
    const float* hidden = (const float*)d_in[0];
    const float* qkv_w  = (const float*)d_in[1];
    const float* qkv_b  = (const float*)d_in[2];
    const float* proj_w = (const float*)d_in[3];
    const float* proj_b = (const float*)d_in[4];
    float* out = (float*)d_out;

    qkv_gemm<<<dim3(3*EMB/BN, MTOT/BM), 256>>>(hidden, qkv_w, qkv_b);

    rope_kernel<<<(BATCH*NH*SEQ*32)/256, 256>>>();

    cudaFuncSetAttribute(attn_kernel, cudaFuncAttributeMaxDynamicSharedMemorySize, 64*1024);
    attn_kernel<<<dim3(SEQ/64, BATCH*NH), 256, 64*1024>>>();

    proj_gemm<<<dim3(EMB/BN, MTOT/BM), 256>>>(proj_w, proj_b, out);
}

// round 14
// speedup vs baseline: 1.0012x; 1.0012x over previous
#include <cuda_runtime.h>
#include <math.h>

#define BATCH 4
#define SEQ   2048
#define EMB   1024
#define NH    16
#define HD    64
#define MTOT  (BATCH*SEQ)

// Scratch (allocation-free rule: device globals)
__device__ float g_q[BATCH*NH*SEQ*HD];
__device__ float g_k[BATCH*NH*SEQ*HD];
__device__ float g_v[BATCH*NH*SEQ*HD];
__device__ float g_ao[MTOT*EMB];

#define BM 128
#define BN 128
#define BK 16

// ---------------------------------------------------------------------------
// QKV GEMM:  C[m,n] = sum_k hidden[m,k] * qkv_w[n,k] + qkv_b[n]
// Epilogue scatters into g_q / g_k / g_v in [B,H,S,hd] layout.
// ---------------------------------------------------------------------------
__global__ void __launch_bounds__(256) qkv_gemm(const float* __restrict__ A,
                                                const float* __restrict__ W,
                                                const float* __restrict__ bias)
{
    __shared__ float sA[BK][BM];
    __shared__ float sB[BK][BN];
    const int K = EMB;
    const int tid = threadIdx.x;
    const int m0 = blockIdx.y * BM;
    const int n0 = blockIdx.x * BN;
    const int tr = tid >> 4;
    const int tc = tid & 15;
    const int lr = tid >> 2;
    const int lc = (tid & 3) << 2;

    float acc[8][8];
#pragma unroll
    for (int i = 0; i < 8; i++)
#pragma unroll
        for (int j = 0; j < 8; j++) acc[i][j] = 0.f;

    const float* Ap = A + (size_t)(m0 + lr) * K + lc;
    const float* Wp = W + (size_t)(n0 + lr) * K + lc;

    for (int k0 = 0; k0 < K; k0 += BK) {
        float4 a0 = *(const float4*)(Ap + k0);
        float4 a1 = *(const float4*)(Ap + (size_t)64 * K + k0);
        float4 b0 = *(const float4*)(Wp + k0);
        float4 b1 = *(const float4*)(Wp + (size_t)64 * K + k0);
        __syncthreads();
        sA[lc+0][lr]    = a0.x; sA[lc+1][lr]    = a0.y; sA[lc+2][lr]    = a0.z; sA[lc+3][lr]    = a0.w;
        sA[lc+0][lr+64] = a1.x; sA[lc+1][lr+64] = a1.y; sA[lc+2][lr+64] = a1.z; sA[lc+3][lr+64] = a1.w;
        sB[lc+0][lr]    = b0.x; sB[lc+1][lr]    = b0.y; sB[lc+2][lr]    = b0.z; sB[lc+3][lr]    = b0.w;
        sB[lc+0][lr+64] = b1.x; sB[lc+1][lr+64] = b1.y; sB[lc+2][lr+64] = b1.z; sB[lc+3][lr+64] = b1.w;
        __syncthreads();
#pragma unroll
        for (int kk = 0; kk < BK; kk++) {
            float4 aL = *(const float4*)&sA[kk][tr*8];
            float4 aH = *(const float4*)&sA[kk][tr*8+4];
            float4 bL = *(const float4*)&sB[kk][tc*8];
            float4 bH = *(const float4*)&sB[kk][tc*8+4];
            float ar[8] = {aL.x,aL.y,aL.z,aL.w,aH.x,aH.y,aH.z,aH.w};
            float br[8] = {bL.x,bL.y,bL.z,bL.w,bH.x,bH.y,bH.z,bH.w};
#pragma unroll
            for (int i = 0; i < 8; i++)
#pragma unroll
                for (int j = 0; j < 8; j++)
                    acc[i][j] = fmaf(ar[i], br[j], acc[i][j]);
        }
    }

    // Epilogue: whole 128-wide N tile stays within one of q/k/v (E=1024 % 128 == 0),
    // and a thread's 8 columns stay within one head (64 % 8 == 0).
    const int which = n0 >> 10;
    float* dst = which == 0 ? g_q : (which == 1 ? g_k : g_v);
    const int bb   = m0 >> 11;                 // SEQ=2048, BM=128 -> tile within one batch
    const int rem0 = (n0 & 1023) + tc * 8;
    const int h    = rem0 >> 6;
    const int d0   = rem0 & 63;
    float4 bv0 = *(const float4*)&bias[n0 + tc*8];
    float4 bv1 = *(const float4*)&bias[n0 + tc*8 + 4];
#pragma unroll
    for (int mi = 0; mi < 8; mi++) {
        int m = m0 + tr * 8 + mi;
        int s = m & (SEQ - 1);
        float* p = dst + (((size_t)(bb * NH + h)) * SEQ + s) * HD + d0;
        float4 v0 = make_float4(acc[mi][0]+bv0.x, acc[mi][1]+bv0.y, acc[mi][2]+bv0.z, acc[mi][3]+bv0.w);
        float4 v1 = make_float4(acc[mi][4]+bv1.x, acc[mi][5]+bv1.y, acc[mi][6]+bv1.z, acc[mi][7]+bv1.w);
        *(float4*)p       = v0;
        *(float4*)(p + 4) = v1;
    }
}

// ---------------------------------------------------------------------------
// Output projection GEMM:  out[m,n] = sum_k g_ao[m,k] * proj_w[n,k] + proj_b[n]
// ---------------------------------------------------------------------------
__global__ void __launch_bounds__(256) proj_gemm(const float* __restrict__ W,
                                                 const float* __restrict__ bias,
                                                 float* __restrict__ C)
{
    __shared__ float sA[BK][BM];
    __shared__ float sB[BK][BN];
    const int K = EMB;
    const int tid = threadIdx.x;
    const int m0 = blockIdx.y * BM;
    const int n0 = blockIdx.x * BN;
    const int tr = tid >> 4;
    const int tc = tid & 15;
    const int lr = tid >> 2;
    const int lc = (tid & 3) << 2;

    float acc[8][8];
#pragma unroll
    for (int i = 0; i < 8; i++)
#pragma unroll
        for (int j = 0; j < 8; j++) acc[i][j] = 0.f;

    const float* Ap = g_ao + (size_t)(m0 + lr) * K + lc;
    const float* Wp = W    + (size_t)(n0 + lr) * K + lc;

    for (int k0 = 0; k0 < K; k0 += BK) {
        float4 a0 = *(const float4*)(Ap + k0);
        float4 a1 = *(const float4*)(Ap + (size_t)64 * K + k0);
        float4 b0 = *(const float4*)(Wp + k0);
        float4 b1 = *(const float4*)(Wp + (size_t)64 * K + k0);
        __syncthreads();
        sA[lc+0][lr]    = a0.x; sA[lc+1][lr]    = a0.y; sA[lc+2][lr]    = a0.z; sA[lc+3][lr]    = a0.w;
        sA[lc+0][lr+64] = a1.x; sA[lc+1][lr+64] = a1.y; sA[lc+2][lr+64] = a1.z; sA[lc+3][lr+64] = a1.w;
        sB[lc+0][lr]    = b0.x; sB[lc+1][lr]    = b0.y; sB[lc+2][lr]    = b0.z; sB[lc+3][lr]    = b0.w;
        sB[lc+0][lr+64] = b1.x; sB[lc+1][lr+64] = b1.y; sB[lc+2][lr+64] = b1.z; sB[lc+3][lr+64] = b1.w;
        __syncthreads();
#pragma unroll
        for (int kk = 0; kk < BK; kk++) {
            float4 aL = *(const float4*)&sA[kk][tr*8];
            float4 aH = *(const float4*)&sA[kk][tr*8+4];
            float4 bL = *(const float4*)&sB[kk][tc*8];
            float4 bH = *(const float4*)&sB[kk][tc*8+4];
            float ar[8] = {aL.x,aL.y,aL.z,aL.w,aH.x,aH.y,aH.z,aH.w};
            float br[8] = {bL.x,bL.y,bL.z,bL.w,bH.x,bH.y,bH.z,bH.w};
#pragma unroll
            for (int i = 0; i < 8; i++)
#pragma unroll
                for (int j = 0; j < 8; j++)
                    acc[i][j] = fmaf(ar[i], br[j], acc[i][j]);
        }
    }

    float4 bv0 = *(const float4*)&bias[n0 + tc*8];
    float4 bv1 = *(const float4*)&bias[n0 + tc*8 + 4];
#pragma unroll
    for (int mi = 0; mi < 8; mi++) {
        int m = m0 + tr * 8 + mi;
        float* p = C + (size_t)m * EMB + n0 + tc * 8;
        float4 v0 = make_float4(acc[mi][0]+bv0.x, acc[mi][1]+bv0.y, acc[mi][2]+bv0.z, acc[mi][3]+bv0.w);
        float4 v1 = make_float4(acc[mi][4]+bv1.x, acc[mi][5]+bv1.y, acc[mi][6]+bv1.z, acc[mi][7]+bv1.w);
        *(float4*)p       = v0;
        *(float4*)(p + 4) = v1;
    }
}

// ---------------------------------------------------------------------------
// RoPE in-place on g_q, g_k. hd=64: pair (j, j+32), j in [0,32).
// Angle in fp64 (cheap; removes trig-precision risk).
// ---------------------------------------------------------------------------
__global__ void rope_kernel()
{
    int t = blockIdx.x * blockDim.x + threadIdx.x;
    int j = t & 31;
    int bhs = t >> 5;
    int s = bhs & (SEQ - 1);
    double inv = exp(-(double)j * (9.210340371976184 / 32.0));  // 10000^(-j/32)
    double th = (double)s * inv;
    float c  = (float)cos(th);
    float si = (float)sin(th);
    float* q = g_q + (size_t)bhs * HD;
    float* k = g_k + (size_t)bhs * HD;
    float x1 = q[j], x2 = q[j + 32];
    q[j]      = x1 * c - x2 * si;
    q[j + 32] = x2 * c + x1 * si;
    x1 = k[j]; x2 = k[j + 32];
    k[j]      = x1 * c - x2 * si;
    k[j + 32] = x2 * c + x1 * si;
}

// ---------------------------------------------------------------------------
// Flash attention fp32. One CTA per (bh, 64-row q tile). 256 threads as 16x16,
// each owning a 4x4 micro-tile. 64 KB dynamic smem:
//   sQt[d][i], sKt[d][j] transposed for conflict-free float4 reads along i/j,
//   sV[j][e] natural, sPt[j][i] transposed for the P@V pass.
// ---------------------------------------------------------------------------
__global__ void __launch_bounds__(256) attn_kernel()
{
    extern __shared__ float sm[];
    float* sQt = sm;
    float* sKt = sm + 64*64;
    float* sV  = sm + 2*64*64;
    float* sPt = sm + 3*64*64;

    const int bh = blockIdx.y;
    const int q0 = blockIdx.x * 64;
    const float* Qg = g_q + ((size_t)bh * SEQ + q0) * HD;
    const float* Kg = g_k + (size_t)bh * SEQ * HD;
    const float* Vg = g_v + (size_t)bh * SEQ * HD;

    const int tid = threadIdx.x;
    const int ty = tid >> 4;
    const int tx = tid & 15;
    const int lrow  = tid >> 2;
    const int lcol4 = (tid & 3) * 4;

    // Load Q tile transposed: sQt[d][i]
#pragma unroll
    for (int rep = 0; rep < 4; rep++) {
        int col = lcol4 + rep * 16;
        float4 v = *(const float4*)&Qg[lrow * HD + col];
        sQt[(col+0)*64 + lrow] = v.x;
        sQt[(col+1)*64 + lrow] = v.y;
        sQt[(col+2)*64 + lrow] = v.z;
        sQt[(col+3)*64 + lrow] = v.w;
    }

    float o[4][4];
    float mrow[4], lsum[4];
#pragma unroll
    for (int i = 0; i < 4; i++) {
        mrow[i] = -1e30f; lsum[i] = 0.f;
#pragma unroll
        for (int e = 0; e < 4; e++) o[i][e] = 0.f;
    }

    for (int nt = 0; nt < SEQ / 64; nt++) {
        const float* Kt = Kg + (size_t)nt * 64 * HD;
        const float* Vt = Vg + (size_t)nt * 64 * HD;
        __syncthreads();   // prior P@V pass done with sV/sPt
#pragma unroll
        for (int rep = 0; rep < 4; rep++) {
            int col = lcol4 + rep * 16;
            float4 kv = *(const float4*)&Kt[lrow * HD + col];
            sKt[(col+0)*64 + lrow] = kv.x;
            sKt[(col+1)*64 + lrow] = kv.y;
            sKt[(col+2)*64 + lrow] = kv.z;
            sKt[(col+3)*64 + lrow] = kv.w;
            float4 vv = *(const float4*)&Vt[lrow * HD + col];
            *(float4*)&sV[lrow * 64 + col] = vv;
        }
        __syncthreads();

        // S = Q K^T
        float s4[4][4];
#pragma unroll
        for (int i = 0; i < 4; i++)
#pragma unroll
            for (int j = 0; j < 4; j++) s4[i][j] = 0.f;
#pragma unroll 16
        for (int d = 0; d < 64; d++) {
            float4 a = *(const float4*)&sQt[d*64 + ty*4];
            float4 b = *(const float4*)&sKt[d*64 + tx*4];
            float aa[4] = {a.x, a.y, a.z, a.w};
            float bb[4] = {b.x, b.y, b.z, b.w};
#pragma unroll
            for (int i = 0; i < 4; i++)
#pragma unroll
                for (int j = 0; j < 4; j++)
                    s4[i][j] = fmaf(aa[i], bb[j], s4[i][j]);
        }

        // Online softmax (row reduction across the 16 tx lanes)
#pragma unroll
        for (int i = 0; i < 4; i++) {
            float mx = -1e30f;
#pragma unroll
            for (int j = 0; j < 4; j++) { s4[i][j] *= 0.125f; mx = fmaxf(mx, s4[i][j]); }
#pragma unroll
            for (int off = 8; off; off >>= 1)
                mx = fmaxf(mx, __shfl_xor_sync(0xffffffffu, mx, off));
            float mnew  = fmaxf(mrow[i], mx);
            float alpha = __expf(mrow[i] - mnew);
            mrow[i] = mnew;
            float rs = 0.f;
#pragma unroll
            for (int j = 0; j < 4; j++) {
                float p = __expf(s4[i][j] - mnew);
                s4[i][j] = p;
                rs += p;
            }
#pragma unroll
            for (int off = 8; off; off >>= 1)
                rs += __shfl_xor_sync(0xffffffffu, rs, off);
            lsum[i] = lsum[i] * alpha + rs;
#pragma unroll
            for (int e = 0; e < 4; e++) o[i][e] *= alpha;
        }

        // Write P transposed: sPt[j][i]
#pragma unroll
        for (int j = 0; j < 4; j++) {
            float4 pv = make_float4(s4[0][j], s4[1][j], s4[2][j], s4[3][j]);
            *(float4*)&sPt[(tx*4 + j)*64 + ty*4] = pv;
        }
        __syncthreads();

        // O += P V
#pragma unroll 16
        for (int j = 0; j < 64; j++) {
            float4 p = *(const float4*)&sPt[j*64 + ty*4];
            float4 v = *(const float4*)&sV[j*64 + tx*4];
            float pa[4] = {p.x, p.y, p.z, p.w};
            float va[4] = {v.x, v.y, v.z, v.w};
#pragma unroll
            for (int i = 0; i < 4; i++)
#pragma unroll
                for (int e = 0; e < 4; e++)
                    o[i][e] = fmaf(pa[i], va[e], o[i][e]);
        }
    }

    // Epilogue: normalize and write [B,S,E] with E index = h*64 + e
    const int bidx = bh >> 4;
    const int h    = bh & 15;
#pragma unroll
    for (int i = 0; i < 4; i++) {
        float inv = 1.f / lsum[i];
        int s = q0 + ty * 4 + i;
        float4 ov = make_float4(o[i][0]*inv, o[i][1]*inv, o[i][2]*inv, o[i][3]*inv);
        *(float4*)&g_ao[((size_t)(bidx * SEQ + s)) * EMB + h * HD + tx * 4] = ov;
    }
}

// ---------------------------------------------------------------------------
extern "C" void kernel_launch(void* const* d_in, const int* in_sizes, int n_in,
                              void* d_out, int out_size)
{
    (void)in_sizes; (void)n_in; (void)out_size;
    const float* hidden = (const float*)d_in[0];
    const float* qkv_w  = (const float*)d_in[1];
    const float* qkv_b  = (const float*)d_in[2];
    const float* proj_w = (const float*)d_in[3];
    const float* proj_b = (const float*)d_in[4];
    float* out = (float*)d_out;

    qkv_gemm<<<dim3(3*EMB/BN, MTOT/BM), 256>>>(hidden, qkv_w, qkv_b);

    rope_kernel<<<(BATCH*NH*SEQ*32)/256, 256>>>();

    cudaFuncSetAttribute(attn_kernel, cudaFuncAttributeMaxDynamicSharedMemorySize, 64*1024);
    attn_kernel<<<dim3(SEQ/64, BATCH*NH), 256, 64*1024>>>();

    proj_gemm<<<dim3(EMB/BN, MTOT/BM), 256>>>(proj_w, proj_b, out);
}